// round 10
// baseline (speedup 1.0000x reference)
#include <cuda_runtime.h>
#include <cuda_fp16.h>
#include <math.h>

#define Bn 16
#define Cn 192
#define HW 4096
#define CHW (Cn*HW)          // 786432
#define NPIX (Bn*CHW)        // 12582912
#define CPG 48
#define NGRP (CPG*HW)        // 196608

// Scratch (device globals: allocation-free rule)
__device__ float g_zconv[NPIX];          // depthwise conv output
__device__ uint4 g_wfrag4[18432];        // fp16 fragment-packed weights
__device__ float g_part[Bn*Cn*2*2];      // per-strip (sum, sumsq) partials
__device__ float g_mu[64];
__device__ float g_rstd[64];

__device__ __forceinline__ unsigned smem_u32(const void* p){
    unsigned a;
    asm("{ .reg .u64 t; cvta.to.shared.u64 t, %1; cvt.u32.u64 %0, t; }"
        : "=r"(a) : "l"(p));
    return a;
}
__device__ __forceinline__ unsigned packh2(float lo, float hi){
    __half2 h = __floats2half2_rn(lo, hi);
    return *reinterpret_cast<unsigned*>(&h);
}
__device__ __forceinline__ float sigm_f(float v){
    return __fdividef(1.0f, 1.0f + __expf(-v));
}
__device__ __forceinline__ float tanh_f(float v){
    float a = __expf(2.0f*v);
    return 1.0f - __fdividef(2.0f, a + 1.0f);
}
__device__ __forceinline__ float gelu_exact(float v){
    return 0.5f*v*(1.0f + erff(v*0.70710678118654752f));
}
// fp16 m16n8k16 MMA, fp32 accumulate
__device__ __forceinline__ void mma_f16(float d[4], uint4 A, uint2 B){
    asm volatile("mma.sync.aligned.m16n8k16.row.col.f32.f16.f16.f32 "
        "{%0,%1,%2,%3}, {%4,%5,%6,%7}, {%8,%9}, {%0,%1,%2,%3};"
        : "+f"(d[0]), "+f"(d[1]), "+f"(d[2]), "+f"(d[3])
        : "r"(A.x), "r"(A.y), "r"(A.z), "r"(A.w), "r"(B.x), "r"(B.y));
}

// ---------------------------------------------------------------------------
// Kernel 0: pack weights in fp16 m16n8k16 A-fragment order (unchanged).
// ---------------------------------------------------------------------------
__global__ __launch_bounds__(256) void setup_wt(const float* __restrict__ pw)
{
    int i4 = blockIdx.x*256 + threadIdx.x;
    if (i4 >= 18432) return;
    int chunk = i4 >> 9, j = i4 & 511;
    int seg = chunk / 12, c = chunk - seg*12;
    int rbl = j >> 7, tm = (j >> 5) & 3, l = j & 31;
    int g = l >> 2, t = l & 3;
    int r  = seg*256 + rbl*64 + tm*16 + g;
    int k0 = c*16 + 2*t;

    #define WVAL(rr, kk) pw[(((rr) & 3)*192 + ((rr) >> 2))*192 + (kk)]
    unsigned w0 = packh2(WVAL(r,   k0  ), WVAL(r,   k0+1));
    unsigned w1 = packh2(WVAL(r+8, k0  ), WVAL(r+8, k0+1));
    unsigned w2 = packh2(WVAL(r,   k0+8), WVAL(r,   k0+9));
    unsigned w3 = packh2(WVAL(r+8, k0+8), WVAL(r+8, k0+9));
    #undef WVAL
    g_wfrag4[i4] = make_uint4(w0, w1, w2, w3);
}

// ---------------------------------------------------------------------------
// Kernel 1: z = x + hidden, depthwise 7x7 conv, per-strip GN partials.
// (unchanged)
// ---------------------------------------------------------------------------
__global__ __launch_bounds__(256) void conv_kernel(
    const float* __restrict__ x, const float* __restrict__ hid,
    const float* __restrict__ dww, const float* __restrict__ dwb)
{
    __shared__ __align__(16) float patch[38][72];
    __shared__ float wsm[49];
    __shared__ float redsum[8], redsq[8];

    int bc    = blockIdx.x;
    int strip = blockIdx.y;
    int c     = bc % Cn;
    int ty0   = strip * 32;
    int base  = bc * HW;
    int tid   = threadIdx.x;

    if (tid < 49) wsm[tid] = dww[c*49 + tid];

    for (int e = tid; e < 38*72; e += 256) {
        int py = e / 72, px = e - py*72;
        int gy = ty0 + py - 3, gx = px - 3;
        float v = 0.f;
        if (px < 70 && gy >= 0 && gy < 64 && gx >= 0 && gx < 64) {
            int gi = base + gy*64 + gx;
            v = __ldg(x + gi) + __ldg(hid + gi);
        }
        patch[py][px] = v;
    }
    __syncthreads();

    float w[49];
    #pragma unroll
    for (int i = 0; i < 49; i++) w[i] = wsm[i];

    int x0 = (tid & 15) << 2;
    int y  = (tid >> 4) << 1;
    float bias = dwb[c];
    float a[2][4];
    #pragma unroll
    for (int j = 0; j < 2; j++)
        #pragma unroll
        for (int i = 0; i < 4; i++) a[j][i] = bias;

    #pragma unroll
    for (int r = 0; r < 8; r++) {
        const float* pr = &patch[y + r][x0];
        float4 q0 = *reinterpret_cast<const float4*>(pr);
        float4 q1 = *reinterpret_cast<const float4*>(pr + 4);
        float4 q2 = *reinterpret_cast<const float4*>(pr + 8);
        float e[10] = {q0.x,q0.y,q0.z,q0.w, q1.x,q1.y,q1.z,q1.w, q2.x,q2.y};
        if (r < 7) {
            #pragma unroll
            for (int kx = 0; kx < 7; kx++) {
                float wv = w[r*7 + kx];
                a[0][0] += wv*e[kx];   a[0][1] += wv*e[kx+1];
                a[0][2] += wv*e[kx+2]; a[0][3] += wv*e[kx+3];
            }
        }
        if (r >= 1) {
            #pragma unroll
            for (int kx = 0; kx < 7; kx++) {
                float wv = w[(r-1)*7 + kx];
                a[1][0] += wv*e[kx];   a[1][1] += wv*e[kx+1];
                a[1][2] += wv*e[kx+2]; a[1][3] += wv*e[kx+3];
            }
        }
    }

    *reinterpret_cast<float4*>(g_zconv + base + (ty0+y)*64 + x0) =
        make_float4(a[0][0], a[0][1], a[0][2], a[0][3]);
    *reinterpret_cast<float4*>(g_zconv + base + (ty0+y+1)*64 + x0) =
        make_float4(a[1][0], a[1][1], a[1][2], a[1][3]);

    float s = 0.f, s2 = 0.f;
    #pragma unroll
    for (int j = 0; j < 2; j++)
        #pragma unroll
        for (int i = 0; i < 4; i++) { s += a[j][i]; s2 += a[j][i]*a[j][i]; }
    #pragma unroll
    for (int o = 16; o > 0; o >>= 1) {
        s  += __shfl_xor_sync(~0u, s,  o);
        s2 += __shfl_xor_sync(~0u, s2, o);
    }
    if ((tid & 31) == 0) { redsum[tid>>5] = s; redsq[tid>>5] = s2; }
    __syncthreads();
    if (tid == 0) {
        float S = 0.f, S2 = 0.f;
        #pragma unroll
        for (int i = 0; i < 8; i++) { S += redsum[i]; S2 += redsq[i]; }
        int pi = (bc*2 + strip)*2;
        g_part[pi] = S; g_part[pi+1] = S2;
    }
}

// ---------------------------------------------------------------------------
// Kernel 2: finalize GN stats (unchanged)
// ---------------------------------------------------------------------------
__global__ __launch_bounds__(128) void stats_kernel()
{
    __shared__ float ss[128], sq[128];
    int gidx = blockIdx.x;
    int b = gidx >> 2, g = gidx & 3;
    int base = (b*Cn + g*CPG) * 2 * 2;
    int tid = threadIdx.x;
    float a = 0.f, q = 0.f;
    if (tid < 96) { a = g_part[base + tid*2]; q = g_part[base + tid*2 + 1]; }
    ss[tid] = a; sq[tid] = q;
    __syncthreads();
    for (int st = 64; st > 0; st >>= 1) {
        if (tid < st) { ss[tid] += ss[tid+st]; sq[tid] += sq[tid+st]; }
        __syncthreads();
    }
    if (tid == 0) {
        float inv = 1.0f / (float)NGRP;
        float mu  = ss[0] * inv;
        float var = sq[0] * inv - mu*mu;
        g_mu[gidx]   = mu;
        g_rstd[gidx] = rsqrtf(var + 1e-5f);
    }
}

// ---------------------------------------------------------------------------
// Kernel 3: fp16 m16n8k16 GEMM, 64-px blocks, 2 CTAs/SM.
// R10: k32 chunks (18 iters), non-aliased weight ring (prefetch before
// staging), two-pass half-K staging.
// smem map:  [0, 24576)               znp fp16 fragment pairs
//            [24576, 73728)           3x 16KB k32 weight chunk ring
//            [73728, 99840)           zs fp32 half-K staging [96][68]
//   aliased: [73728, 90368)           epilogue transpose buffer
// ---------------------------------------------------------------------------
#define WB_OFF  24576
#define WBUFSZ  16384
#define ZS_OFF  73728
#define EPI_OFF 73728
#define EPISTR  260
#define GSMEM   99840

__global__ __launch_bounds__(256,2) void gemm_kernel(
    const float* __restrict__ ctx, const float* __restrict__ cell,
    const float* __restrict__ pwb, float* __restrict__ out)
{
    extern __shared__ __align__(16) char smem[];
    int tid = threadIdx.x;
    int b   = blockIdx.x >> 6;
    int hw0 = (blockIdx.x & 63) << 6;
    int wid = tid >> 5, l = tid & 31;
    int g = l >> 2, t4 = l & 3;
    int wm = wid & 3, wn = wid >> 2;

    // cp.async k32 weight chunk (1024 uint4 = 4 per thread)
    auto issue_chunk = [&](int n){
        const uint4* src = g_wfrag4 + (size_t)n*1024 + tid;
        unsigned sa = smem_u32(smem + WB_OFF + (n % 3)*WBUFSZ + tid*16);
        #pragma unroll
        for (int f = 0; f < 4; f++)
            asm volatile("cp.async.cg.shared.global [%0], [%1], 16;"
                         :: "r"(sa + f*4096), "l"(src + f*256));
        asm volatile("cp.async.commit_group;" ::: "memory");
    };
    // prefetch the first two chunks BEFORE staging (wb no longer aliases zs)
    issue_chunk(0);
    issue_chunk(1);

    // ---- two-pass staging: GN/FiLM fused, fp16 fragment-pair packing ----
    const float* zc = g_zconv + (size_t)b*CHW + hw0;
    const float* cs = ctx + (size_t)b*2*CHW + hw0;
    float* zs = reinterpret_cast<float*>(smem + ZS_OFF);
    #pragma unroll
    for (int pass = 0; pass < 2; pass++) {
        int kbase = pass*96;
        // load + GN/FiLM -> fp32 zs[96][68]
        #pragma unroll
        for (int i = 0; i < 6; i++) {
            int idx = tid + i*256;               // over 96*16 float4 slots
            int k = idx >> 4, p4 = (idx & 15) << 2;
            int kg = kbase + k;
            float4 cv = __ldg(reinterpret_cast<const float4*>(
                              zc + (size_t)kg*HW + p4));
            float4 sc = __ldg(reinterpret_cast<const float4*>(
                              cs + (size_t)kg*HW + p4));
            float4 bi = __ldg(reinterpret_cast<const float4*>(
                              cs + (size_t)(kg + Cn)*HW + p4));
            int gi = (b << 2) + ((kg*683) >> 15);
            float mu = g_mu[gi], rs = g_rstd[gi];
            float4 o;
            o.x = (cv.x - mu)*rs*(1.0f + sc.x) + bi.x;
            o.y = (cv.y - mu)*rs*(1.0f + sc.y) + bi.y;
            o.z = (cv.z - mu)*rs*(1.0f + sc.z) + bi.z;
            o.w = (cv.w - mu)*rs*(1.0f + sc.w) + bi.w;
            *reinterpret_cast<float4*>(zs + k*68 + p4) = o;
        }
        __syncthreads();
        // pack -> fp16 fragment pairs (znp), c16 = pass*6 .. +5
        {
            int px = tid >> 2, tt = tid & 3;
            #pragma unroll
            for (int cc = 0; cc < 6; cc++) {
                int c = pass*6 + cc;
                int k0 = cc*16 + tt*2;            // local k in zs
                float z0 = zs[ k0   *68 + px];
                float z1 = zs[(k0+1)*68 + px];
                float z2 = zs[(k0+8)*68 + px];
                float z3 = zs[(k0+9)*68 + px];
                *reinterpret_cast<uint2*>(smem + ((c*64 + px)*4 + tt)*8) =
                    make_uint2(packh2(z0, z1), packh2(z2, z3));
            }
        }
        __syncthreads();
    }

    float D[4][4][4];
    #pragma unroll
    for (int i = 0; i < 4; i++)
        #pragma unroll
        for (int j = 0; j < 4; j++)
            #pragma unroll
            for (int q = 0; q < 4; q++) D[i][j][q] = 0.f;

    for (int seg = 0; seg < 3; seg++) {
        for (int c32 = 0; c32 < 6; c32++) {
            int gc = seg*6 + c32;
            if (gc < 17)
                asm volatile("cp.async.wait_group 1;" ::: "memory");
            else
                asm volatile("cp.async.wait_group 0;" ::: "memory");
            __syncthreads();
            if (gc + 2 < 18) issue_chunk(gc + 2);

            const char* wb = smem + WB_OFF + (gc % 3)*WBUFSZ;
            #pragma unroll
            for (int h = 0; h < 2; h++) {
                int c16 = c32*2 + h;
                uint2 Bf[4];
                uint4 Af[4];
                #pragma unroll
                for (int tn = 0; tn < 4; tn++) {
                    int p = wn*32 + tn*8 + g;
                    Bf[tn] = *reinterpret_cast<const uint2*>(
                                smem + ((c16*64 + p)*4 + t4)*8);
                }
                #pragma unroll
                for (int tm = 0; tm < 4; tm++)
                    Af[tm] = *reinterpret_cast<const uint4*>(
                                wb + h*8192 + ((wm*4 + tm)*32 + l)*16);
                #pragma unroll
                for (int tm = 0; tm < 4; tm++)
                    #pragma unroll
                    for (int tn = 0; tn < 4; tn++)
                        mma_f16(D[tm][tn], Af[tm], Bf[tn]);
            }
        }

        // ---- epilogue for seg: 4 phases of 16 px (unchanged map) ----
        {
            float* ep = reinterpret_cast<float*>(smem + EPI_OFF);
            int chl = tid >> 2;
            int pq  = tid & 3;
            int ch  = seg*64 + chl;
            float bfc = __ldg(pwb + ch),       bic = __ldg(pwb + 192 + ch);
            float bgc = __ldg(pwb + 384 + ch), boc = __ldg(pwb + 576 + ch);
            size_t gb0 = (size_t)b*CHW + (size_t)ch*HW + hw0 + pq*4;
            float4 cellv[4];
            #pragma unroll
            for (int ph = 0; ph < 4; ph++)
                cellv[ph] = __ldg(reinterpret_cast<const float4*>(
                                  cell + gb0 + ph*16));
            #pragma unroll 1
            for (int ph = 0; ph < 4; ph++) {
                if (wn == (ph >> 1)) {
                    int tnb = (ph & 1) * 2;
                    #pragma unroll
                    for (int tm = 0; tm < 4; tm++)
                        #pragma unroll
                        for (int tj = 0; tj < 2; tj++) {
                            int tn = tnb + tj;
                            int row = wm*64 + tm*16 + g;
                            int pxl = tj*8 + 2*t4;
                            ep[ pxl   *EPISTR + row    ] = D[tm][tn][0];
                            ep[(pxl+1)*EPISTR + row    ] = D[tm][tn][1];
                            ep[ pxl   *EPISTR + row + 8] = D[tm][tn][2];
                            ep[(pxl+1)*EPISTR + row + 8] = D[tm][tn][3];
                        }
                }
                __syncthreads();
                size_t gbase = gb0 + ph*16;
                float cold[4] = {cellv[ph].x, cellv[ph].y,
                                 cellv[ph].z, cellv[ph].w};
                float hn[4], cn[4];
                #pragma unroll
                for (int j = 0; j < 4; j++) {
                    float4 gv = *reinterpret_cast<const float4*>(
                                ep + (pq*4 + j)*EPISTR + chl*4);
                    float fv = gv.x + bfc, iv = gv.y + bic;
                    float gg = gv.z + bgc, ov = gv.w + boc;
                    float cv = sigm_f(fv)*cold[j] + sigm_f(iv)*tanh_f(gg);
                    cn[j] = cv;
                    hn[j] = sigm_f(ov) * gelu_exact(cv);
                }
                *reinterpret_cast<float4*>(out + gbase) =
                    make_float4(hn[0], hn[1], hn[2], hn[3]);
                *reinterpret_cast<float4*>(out + NPIX + gbase) =
                    make_float4(cn[0], cn[1], cn[2], cn[3]);
                __syncthreads();
            }
        }
        // reset accumulators for next seg
        #pragma unroll
        for (int i = 0; i < 4; i++)
            #pragma unroll
            for (int j = 0; j < 4; j++)
                #pragma unroll
                for (int q = 0; q < 4; q++) D[i][j][q] = 0.f;
    }
}

// ---------------------------------------------------------------------------
extern "C" void kernel_launch(void* const* d_in, const int* in_sizes, int n_in,
                              void* d_out, int out_size)
{
    const float* x      = (const float*)d_in[0];
    const float* hidden = (const float*)d_in[1];
    const float* cell   = (const float*)d_in[2];
    const float* ctx    = (const float*)d_in[3];
    const float* dww    = (const float*)d_in[4];
    const float* dwb    = (const float*)d_in[5];
    const float* pw     = (const float*)d_in[6];
    const float* pwb    = (const float*)d_in[7];
    float* out = (float*)d_out;

    cudaFuncSetAttribute(gemm_kernel,
                         cudaFuncAttributeMaxDynamicSharedMemorySize, GSMEM);

    setup_wt<<<72, 256>>>(pw);
    conv_kernel<<<dim3(Bn*Cn, 2), 256>>>(x, hidden, dww, dwb);
    stats_kernel<<<64, 128>>>();
    gemm_kernel<<<1024, 256, GSMEM>>>(ctx, cell, pwb, out);
}

// round 11
// speedup vs baseline: 1.2532x; 1.2532x over previous
#include <cuda_runtime.h>
#include <cuda_fp16.h>
#include <math.h>

#define Bn 16
#define Cn 192
#define HW 4096
#define CHW (Cn*HW)          // 786432
#define NPIX (Bn*CHW)        // 12582912
#define CPG 48
#define NGRP (CPG*HW)        // 196608

// Scratch (device globals: allocation-free rule)
__device__ float g_zconv[NPIX];          // depthwise conv output
__device__ uint4 g_wfrag4[18432];        // fp16 fragment-packed weights
__device__ float g_part[Bn*Cn*2*2];      // per-strip (sum, sumsq) partials
__device__ float g_mu[64];
__device__ float g_rstd[64];

__device__ __forceinline__ unsigned smem_u32(const void* p){
    unsigned a;
    asm("{ .reg .u64 t; cvta.to.shared.u64 t, %1; cvt.u32.u64 %0, t; }"
        : "=r"(a) : "l"(p));
    return a;
}
__device__ __forceinline__ unsigned packh2(float lo, float hi){
    __half2 h = __floats2half2_rn(lo, hi);
    return *reinterpret_cast<unsigned*>(&h);
}
__device__ __forceinline__ float sigm_f(float v){
    return __fdividef(1.0f, 1.0f + __expf(-v));
}
__device__ __forceinline__ float tanh_f(float v){
    float a = __expf(2.0f*v);
    return 1.0f - __fdividef(2.0f, a + 1.0f);
}
__device__ __forceinline__ float gelu_exact(float v){
    return 0.5f*v*(1.0f + erff(v*0.70710678118654752f));
}
// fp16 m16n8k16 MMA, fp32 accumulate
__device__ __forceinline__ void mma_f16(float d[4], uint4 A, uint2 B){
    asm volatile("mma.sync.aligned.m16n8k16.row.col.f32.f16.f16.f32 "
        "{%0,%1,%2,%3}, {%4,%5,%6,%7}, {%8,%9}, {%0,%1,%2,%3};"
        : "+f"(d[0]), "+f"(d[1]), "+f"(d[2]), "+f"(d[3])
        : "r"(A.x), "r"(A.y), "r"(A.z), "r"(A.w), "r"(B.x), "r"(B.y));
}

// ---------------------------------------------------------------------------
// Kernel 0: pack weights in fp16 m16n8k16 A-fragment order for 128-row segs.
// chunk = seg6*12 + c (72 chunks of 128 rows x k16); within chunk:
//   slot = wm*2 + tm (8), lane l. uint4 i4 = chunk*256 + slot*32 + l
//   r = seg6*128 + wm*32 + tm*16 + g ; k0 = c*16 + 2*t
//   regs: {A[r][k0..+1] | A[r+8][k0..+1] | A[r][k0+8..+9] | A[r+8][k0+8..+9]}
// ---------------------------------------------------------------------------
__global__ __launch_bounds__(256) void setup_wt(const float* __restrict__ pw)
{
    int i4 = blockIdx.x*256 + threadIdx.x;
    if (i4 >= 18432) return;
    int chunk = i4 >> 8, j = i4 & 255;
    int seg6 = chunk / 12, c = chunk - seg6*12;
    int slot = j >> 5, l = j & 31;
    int g = l >> 2, t = l & 3;
    int r  = seg6*128 + (slot >> 1)*32 + (slot & 1)*16 + g;
    int k0 = c*16 + 2*t;

    #define WVAL(rr, kk) pw[(((rr) & 3)*192 + ((rr) >> 2))*192 + (kk)]
    unsigned w0 = packh2(WVAL(r,   k0  ), WVAL(r,   k0+1));
    unsigned w1 = packh2(WVAL(r+8, k0  ), WVAL(r+8, k0+1));
    unsigned w2 = packh2(WVAL(r,   k0+8), WVAL(r,   k0+9));
    unsigned w3 = packh2(WVAL(r+8, k0+8), WVAL(r+8, k0+9));
    #undef WVAL
    g_wfrag4[i4] = make_uint4(w0, w1, w2, w3);
}

// ---------------------------------------------------------------------------
// Kernel 1: z = x + hidden, depthwise 7x7 conv, per-strip GN partials.
// (unchanged)
// ---------------------------------------------------------------------------
__global__ __launch_bounds__(256) void conv_kernel(
    const float* __restrict__ x, const float* __restrict__ hid,
    const float* __restrict__ dww, const float* __restrict__ dwb)
{
    __shared__ __align__(16) float patch[38][72];
    __shared__ float wsm[49];
    __shared__ float redsum[8], redsq[8];

    int bc    = blockIdx.x;
    int strip = blockIdx.y;
    int c     = bc % Cn;
    int ty0   = strip * 32;
    int base  = bc * HW;
    int tid   = threadIdx.x;

    if (tid < 49) wsm[tid] = dww[c*49 + tid];

    for (int e = tid; e < 38*72; e += 256) {
        int py = e / 72, px = e - py*72;
        int gy = ty0 + py - 3, gx = px - 3;
        float v = 0.f;
        if (px < 70 && gy >= 0 && gy < 64 && gx >= 0 && gx < 64) {
            int gi = base + gy*64 + gx;
            v = __ldg(x + gi) + __ldg(hid + gi);
        }
        patch[py][px] = v;
    }
    __syncthreads();

    float w[49];
    #pragma unroll
    for (int i = 0; i < 49; i++) w[i] = wsm[i];

    int x0 = (tid & 15) << 2;
    int y  = (tid >> 4) << 1;
    float bias = dwb[c];
    float a[2][4];
    #pragma unroll
    for (int j = 0; j < 2; j++)
        #pragma unroll
        for (int i = 0; i < 4; i++) a[j][i] = bias;

    #pragma unroll
    for (int r = 0; r < 8; r++) {
        const float* pr = &patch[y + r][x0];
        float4 q0 = *reinterpret_cast<const float4*>(pr);
        float4 q1 = *reinterpret_cast<const float4*>(pr + 4);
        float4 q2 = *reinterpret_cast<const float4*>(pr + 8);
        float e[10] = {q0.x,q0.y,q0.z,q0.w, q1.x,q1.y,q1.z,q1.w, q2.x,q2.y};
        if (r < 7) {
            #pragma unroll
            for (int kx = 0; kx < 7; kx++) {
                float wv = w[r*7 + kx];
                a[0][0] += wv*e[kx];   a[0][1] += wv*e[kx+1];
                a[0][2] += wv*e[kx+2]; a[0][3] += wv*e[kx+3];
            }
        }
        if (r >= 1) {
            #pragma unroll
            for (int kx = 0; kx < 7; kx++) {
                float wv = w[(r-1)*7 + kx];
                a[1][0] += wv*e[kx];   a[1][1] += wv*e[kx+1];
                a[1][2] += wv*e[kx+2]; a[1][3] += wv*e[kx+3];
            }
        }
    }

    *reinterpret_cast<float4*>(g_zconv + base + (ty0+y)*64 + x0) =
        make_float4(a[0][0], a[0][1], a[0][2], a[0][3]);
    *reinterpret_cast<float4*>(g_zconv + base + (ty0+y+1)*64 + x0) =
        make_float4(a[1][0], a[1][1], a[1][2], a[1][3]);

    float s = 0.f, s2 = 0.f;
    #pragma unroll
    for (int j = 0; j < 2; j++)
        #pragma unroll
        for (int i = 0; i < 4; i++) { s += a[j][i]; s2 += a[j][i]*a[j][i]; }
    #pragma unroll
    for (int o = 16; o > 0; o >>= 1) {
        s  += __shfl_xor_sync(~0u, s,  o);
        s2 += __shfl_xor_sync(~0u, s2, o);
    }
    if ((tid & 31) == 0) { redsum[tid>>5] = s; redsq[tid>>5] = s2; }
    __syncthreads();
    if (tid == 0) {
        float S = 0.f, S2 = 0.f;
        #pragma unroll
        for (int i = 0; i < 8; i++) { S += redsum[i]; S2 += redsq[i]; }
        int pi = (bc*2 + strip)*2;
        g_part[pi] = S; g_part[pi+1] = S2;
    }
}

// ---------------------------------------------------------------------------
// Kernel 2: finalize GN stats (unchanged)
// ---------------------------------------------------------------------------
__global__ __launch_bounds__(128) void stats_kernel()
{
    __shared__ float ss[128], sq[128];
    int gidx = blockIdx.x;
    int b = gidx >> 2, g = gidx & 3;
    int base = (b*Cn + g*CPG) * 2 * 2;
    int tid = threadIdx.x;
    float a = 0.f, q = 0.f;
    if (tid < 96) { a = g_part[base + tid*2]; q = g_part[base + tid*2 + 1]; }
    ss[tid] = a; sq[tid] = q;
    __syncthreads();
    for (int st = 64; st > 0; st >>= 1) {
        if (tid < st) { ss[tid] += ss[tid+st]; sq[tid] += sq[tid+st]; }
        __syncthreads();
    }
    if (tid == 0) {
        float inv = 1.0f / (float)NGRP;
        float mu  = ss[0] * inv;
        float var = sq[0] * inv - mu*mu;
        g_mu[gidx]   = mu;
        g_rstd[gidx] = rsqrtf(var + 1e-5f);
    }
}

// ---------------------------------------------------------------------------
// Kernel 3: fp16 m16n8k16 GEMM, 64-px x 768 rows in 6 segs of 128 rows.
// 256 thr: wm = wid&3 (4x32 rows), wn = wid>>2 (2x32 px). D = 32 regs.
// Target 3 CTAs/SM (regs <= 84, smem 66560).
// smem map:  [0, 24576)       znp fp16 fragment pairs
//            [24576, 49152)   3x 8KB k32 weight chunk ring
//            [49152, 66560)   zs fp32 staging [64][68] / epilogue buffer
// ---------------------------------------------------------------------------
#define WB_OFF  24576
#define WBUFSZ  8192
#define ZS_OFF  49152
#define EPI_OFF 49152
#define EPISTR  132
#define GSMEM   66560

__global__ __launch_bounds__(256,3) void gemm_kernel(
    const float* __restrict__ ctx, const float* __restrict__ cell,
    const float* __restrict__ pwb, float* __restrict__ out)
{
    extern __shared__ __align__(16) char smem[];
    int tid = threadIdx.x;
    int b   = blockIdx.x >> 6;
    int hw0 = (blockIdx.x & 63) << 6;
    int wid = tid >> 5, l = tid & 31;
    int g = l >> 2, t4 = l & 3;
    int wm = wid & 3, wn = wid >> 2;

    // cp.async k32 weight chunk n (512 uint4 = 2 per thread)
    auto issue_chunk = [&](int n){
        int base4 = ((n/6)*12 + (n%6)*2) * 256;
        const uint4* src = g_wfrag4 + base4 + tid;
        unsigned sa = smem_u32(smem + WB_OFF + (n % 3)*WBUFSZ + tid*16);
        asm volatile("cp.async.cg.shared.global [%0], [%1], 16;"
                     :: "r"(sa), "l"(src));
        asm volatile("cp.async.cg.shared.global [%0], [%1], 16;"
                     :: "r"(sa + 4096), "l"(src + 256));
        asm volatile("cp.async.commit_group;" ::: "memory");
    };
    issue_chunk(0);
    issue_chunk(1);

    // ---- three-pass staging: GN/FiLM fused, fp16 fragment-pair packing ----
    const float* zc = g_zconv + (size_t)b*CHW + hw0;
    const float* cs = ctx + (size_t)b*2*CHW + hw0;
    float* zs = reinterpret_cast<float*>(smem + ZS_OFF);
    #pragma unroll
    for (int pass = 0; pass < 3; pass++) {
        int kbase = pass*64;
        #pragma unroll
        for (int i = 0; i < 4; i++) {
            int idx = tid + i*256;               // over 64*16 float4 slots
            int k = idx >> 4, p4 = (idx & 15) << 2;
            int kg = kbase + k;
            float4 cv = __ldg(reinterpret_cast<const float4*>(
                              zc + (size_t)kg*HW + p4));
            float4 sc = __ldg(reinterpret_cast<const float4*>(
                              cs + (size_t)kg*HW + p4));
            float4 bi = __ldg(reinterpret_cast<const float4*>(
                              cs + (size_t)(kg + Cn)*HW + p4));
            int gi = (b << 2) + ((kg*683) >> 15);
            float mu = g_mu[gi], rs = g_rstd[gi];
            float4 o;
            o.x = (cv.x - mu)*rs*(1.0f + sc.x) + bi.x;
            o.y = (cv.y - mu)*rs*(1.0f + sc.y) + bi.y;
            o.z = (cv.z - mu)*rs*(1.0f + sc.z) + bi.z;
            o.w = (cv.w - mu)*rs*(1.0f + sc.w) + bi.w;
            *reinterpret_cast<float4*>(zs + k*68 + p4) = o;
        }
        __syncthreads();
        {
            int px = tid >> 2, tt = tid & 3;
            #pragma unroll
            for (int cc = 0; cc < 4; cc++) {
                int c = pass*4 + cc;
                int k0 = cc*16 + tt*2;            // local k in zs
                float z0 = zs[ k0   *68 + px];
                float z1 = zs[(k0+1)*68 + px];
                float z2 = zs[(k0+8)*68 + px];
                float z3 = zs[(k0+9)*68 + px];
                *reinterpret_cast<uint2*>(smem + ((c*64 + px)*4 + tt)*8) =
                    make_uint2(packh2(z0, z1), packh2(z2, z3));
            }
        }
        __syncthreads();
    }

    float D[2][4][4];
    #pragma unroll
    for (int i = 0; i < 2; i++)
        #pragma unroll
        for (int j = 0; j < 4; j++)
            #pragma unroll
            for (int q = 0; q < 4; q++) D[i][j][q] = 0.f;

    for (int seg = 0; seg < 6; seg++) {
        for (int c32 = 0; c32 < 6; c32++) {
            int gc = seg*6 + c32;
            if (gc < 35)
                asm volatile("cp.async.wait_group 1;" ::: "memory");
            else
                asm volatile("cp.async.wait_group 0;" ::: "memory");
            __syncthreads();
            if (gc + 2 < 36) issue_chunk(gc + 2);

            const char* wb = smem + WB_OFF + (gc % 3)*WBUFSZ;
            #pragma unroll
            for (int h = 0; h < 2; h++) {
                int c16 = c32*2 + h;
                uint2 Bf[4];
                uint4 Af[2];
                #pragma unroll
                for (int tn = 0; tn < 4; tn++) {
                    int p = wn*32 + tn*8 + g;
                    Bf[tn] = *reinterpret_cast<const uint2*>(
                                smem + ((c16*64 + p)*4 + t4)*8);
                }
                #pragma unroll
                for (int tm = 0; tm < 2; tm++)
                    Af[tm] = *reinterpret_cast<const uint4*>(
                                wb + h*4096 + ((wm*2 + tm)*32 + l)*16);
                #pragma unroll
                for (int tm = 0; tm < 2; tm++)
                    #pragma unroll
                    for (int tn = 0; tn < 4; tn++)
                        mma_f16(D[tm][tn], Af[tm], Bf[tn]);
            }
        }

        // ---- epilogue for seg (32 channels): 2 phases of 32 px ----
        {
            float* ep = reinterpret_cast<float*>(smem + EPI_OFF);
            int chl = tid >> 3;           // 0..31 local channel
            int pq  = tid & 7;            // 4 px each
            int ch  = seg*32 + chl;
            float bfc = __ldg(pwb + ch),       bic = __ldg(pwb + 192 + ch);
            float bgc = __ldg(pwb + 384 + ch), boc = __ldg(pwb + 576 + ch);
            size_t gb0 = (size_t)b*CHW + (size_t)ch*HW + hw0 + pq*4;
            float4 cellv[2];
            #pragma unroll
            for (int ph = 0; ph < 2; ph++)
                cellv[ph] = __ldg(reinterpret_cast<const float4*>(
                                  cell + gb0 + ph*32));
            #pragma unroll 1
            for (int ph = 0; ph < 2; ph++) {
                if (wn == ph) {
                    #pragma unroll
                    for (int tm = 0; tm < 2; tm++)
                        #pragma unroll
                        for (int tn = 0; tn < 4; tn++) {
                            int row = wm*32 + tm*16 + g;
                            int pxl = tn*8 + 2*t4;
                            ep[ pxl   *EPISTR + row    ] = D[tm][tn][0];
                            ep[(pxl+1)*EPISTR + row    ] = D[tm][tn][1];
                            ep[ pxl   *EPISTR + row + 8] = D[tm][tn][2];
                            ep[(pxl+1)*EPISTR + row + 8] = D[tm][tn][3];
                        }
                }
                __syncthreads();
                size_t gbase = gb0 + ph*32;
                float cold[4] = {cellv[ph].x, cellv[ph].y,
                                 cellv[ph].z, cellv[ph].w};
                float hn[4], cn[4];
                #pragma unroll
                for (int j = 0; j < 4; j++) {
                    float4 gv = *reinterpret_cast<const float4*>(
                                ep + (pq*4 + j)*EPISTR + chl*4);
                    float fv = gv.x + bfc, iv = gv.y + bic;
                    float gg = gv.z + bgc, ov = gv.w + boc;
                    float cv = sigm_f(fv)*cold[j] + sigm_f(iv)*tanh_f(gg);
                    cn[j] = cv;
                    hn[j] = sigm_f(ov) * gelu_exact(cv);
                }
                *reinterpret_cast<float4*>(out + gbase) =
                    make_float4(hn[0], hn[1], hn[2], hn[3]);
                *reinterpret_cast<float4*>(out + NPIX + gbase) =
                    make_float4(cn[0], cn[1], cn[2], cn[3]);
                __syncthreads();
            }
        }
        // reset accumulators for next seg
        #pragma unroll
        for (int i = 0; i < 2; i++)
            #pragma unroll
            for (int j = 0; j < 4; j++)
                #pragma unroll
                for (int q = 0; q < 4; q++) D[i][j][q] = 0.f;
    }
}

// ---------------------------------------------------------------------------
extern "C" void kernel_launch(void* const* d_in, const int* in_sizes, int n_in,
                              void* d_out, int out_size)
{
    const float* x      = (const float*)d_in[0];
    const float* hidden = (const float*)d_in[1];
    const float* cell   = (const float*)d_in[2];
    const float* ctx    = (const float*)d_in[3];
    const float* dww    = (const float*)d_in[4];
    const float* dwb    = (const float*)d_in[5];
    const float* pw     = (const float*)d_in[6];
    const float* pwb    = (const float*)d_in[7];
    float* out = (float*)d_out;

    cudaFuncSetAttribute(gemm_kernel,
                         cudaFuncAttributeMaxDynamicSharedMemorySize, GSMEM);

    setup_wt<<<72, 256>>>(pw);
    conv_kernel<<<dim3(Bn*Cn, 2), 256>>>(x, hidden, dww, dwb);
    stats_kernel<<<64, 128>>>();
    gemm_kernel<<<1024, 256, GSMEM>>>(ctx, cell, pwb, out);
}